// round 17
// baseline (speedup 1.0000x reference)
#include <cuda_runtime.h>
#include <cuda_bf16.h>
#include <cstdint>

// Problem constants
#define BATCH   8192
#define R_DIM   8
#define PH_DIM  16
#define PAIRS   1024
#define OUT_U   8192   // PAIRS * R

#define PK_NCHUNK 32         // 32 pair chunks of 32 pairs
#define MK_TILE   64
#define MK_NTILE  (BATCH / MK_TILE)   // 128
#define N_SLICES  (PK_NCHUNK + 2)     // 34
#define ARRIVALS  40                  // 32 pair CTAs + 8 mlp CTAs per 256-sample tile

typedef unsigned long long ull;

// Deterministic partial buffer: 32 interaction chunks + X + Z
__device__ float g_partial[N_SLICES * BATCH];
// Transposed inputs: [32][8192]
__device__ float g_xT[32 * BATCH];
__device__ float g_zT[32 * BATCH];
// Per-256-sample-tile arrival counters (zero-init; reducer resets -> replay-safe)
__device__ int g_cnt[32];

// ---- packed f32x2 helpers ---------------------------------------------------
__device__ __forceinline__ ull pack2(float lo, float hi) {
    ull r;
    asm("mov.b64 %0, {%1, %2};" : "=l"(r) : "f"(lo), "f"(hi));
    return r;
}
__device__ __forceinline__ void unpack2(ull v, float& lo, float& hi) {
    asm("mov.b64 {%0, %1}, %2;" : "=f"(lo), "=f"(hi) : "l"(v));
}
__device__ __forceinline__ ull fma2(ull a, ull b, ull c) {
    ull d;
    asm("fma.rn.f32x2 %0, %1, %2, %3;" : "=l"(d) : "l"(a), "l"(b), "l"(c));
    return d;
}
__device__ __forceinline__ uint32_t tf32_rna(float v) {
    uint32_t u;
    asm("cvt.rna.tf32.f32 %0, %1;" : "=r"(u) : "f"(v));
    return u;
}
// mma.sync m16n8k8 tf32: D = A(16x8,row) * B(8x8,col) + C  (fp32 accum)
__device__ __forceinline__ void mma_tf32(float& d0, float& d1, float& d2, float& d3,
                                         uint32_t a0, uint32_t a1, uint32_t a2, uint32_t a3,
                                         uint32_t b0, uint32_t b1) {
    asm volatile(
        "mma.sync.aligned.m16n8k8.row.col.f32.tf32.tf32.f32 "
        "{%0,%1,%2,%3}, {%4,%5,%6,%7}, {%8,%9}, {%0,%1,%2,%3};\n"
        : "+f"(d0), "+f"(d1), "+f"(d2), "+f"(d3)
        : "r"(a0), "r"(a1), "r"(a2), "r"(a3), "r"(b0), "r"(b1));
}

// Fixed ascending per-sample reduction chain — IDENTICAL in both kernels so the
// output is bit-identical no matter which CTA performs it.
__device__ __forceinline__ float reduce_sample(int smp) {
    float s = 0.0f;
    #pragma unroll
    for (int c = 0; c < N_SLICES; ++c)
        s += g_partial[c * BATCH + smp];
    return s;
}

// ---------------------------------------------------------------------------
// Kernel 0: transpose x,z [8192][32] -> [32][8192]
// ---------------------------------------------------------------------------
__global__ __launch_bounds__(256)
void transpose_kernel(const float* __restrict__ x, const float* __restrict__ z)
{
    __shared__ float tx[64 * 33];
    __shared__ float tz[64 * 33];
    const int tid = threadIdx.x;
    const int g0  = blockIdx.x * 64;

    for (int idx = tid; idx < 64 * 32; idx += 256) {
        int s = idx >> 5, c = idx & 31;
        tx[s * 33 + c] = x[(size_t)g0 * 32 + idx];
        tz[s * 33 + c] = z[(size_t)g0 * 32 + idx];
    }
    __syncthreads();
    for (int idx = tid; idx < 64 * 32; idx += 256) {
        int c = idx >> 6, s = idx & 63;
        g_xT[(size_t)c * BATCH + g0 + s] = tx[s * 33 + c];
        g_zT[(size_t)c * BATCH + g0 + s] = tz[s * 33 + c];
    }
}

// ---------------------------------------------------------------------------
// Kernel 1: main-effect MLPs (32->128->64->1). blockIdx.y = part (x or z).
// MK_TILE=64, 256 threads. Phases 1 AND 2 via tf32 mma, phase 3 SIMT.
// smem (floats): in 0 (64x36) | h1 2304..(64x132) | w1f 10752 (4096)
//   | w2f 14848 (8192) | h2 23040 (64x68) | w3 27392 | b1 27456 | b2 27584
//   total 27648 floats = 110592 B
// ---------------------------------------------------------------------------
__global__ __launch_bounds__(256)
void mlp_kernel(float* __restrict__ out,
                const float* __restrict__ x, const float* __restrict__ z,
                const float* __restrict__ xw1, const float* __restrict__ xb1,
                const float* __restrict__ xw2, const float* __restrict__ xb2,
                const float* __restrict__ xw3, const float* __restrict__ xb3,
                const float* __restrict__ zw1, const float* __restrict__ zb1,
                const float* __restrict__ zw2, const float* __restrict__ zb2,
                const float* __restrict__ zw3, const float* __restrict__ zb3)
{
    extern __shared__ float sm[];
    float* in_sm  = sm;                 // 64*36  = 2304 (pad 36 -> conflict-free A-frag LDS)
    float* h1_sm  = sm + 2304;          // 64*132 = 8448
    float* w1f_sm = sm + 10752;         // 4096 (w1 tf32 B-frags)
    float* w2f_sm = sm + 14848;         // 8192 (w2 tf32 B-frags)
    float* h2_sm  = sm + 23040;         // 64*68 = 4352
    float* w3_sm  = sm + 27392;         // 64
    float* b1_sm  = sm + 27456;         // 128
    float* b2_sm  = sm + 27584;         // 64

    const int tid  = threadIdx.x;
    const int tile = blockIdx.x;
    const int part = blockIdx.y;
    const int g0   = tile * MK_TILE;

    const float* in = part ? z   : x;
    const float* w1 = part ? zw1 : xw1;
    const float* b1 = part ? zb1 : xb1;
    const float* w2 = part ? zw2 : xw2;
    const float* b2 = part ? zb2 : xb2;
    const float* w3 = part ? zw3 : xw3;
    const float* b3 = part ? zb3 : xb3;

    for (int idx = tid; idx < MK_TILE * 32; idx += 256) {
        int s = idx >> 5, c = idx & 31;
        in_sm[s * 36 + c] = in[(size_t)g0 * 32 + idx];
    }
    // stage w1 [32,128] into tf32 B-frag order:
    // idx = (kk*16 + nt)*64 + ln*2 + hf ; k = kk*8+(ln&3)+(hf<<2), n = nt*8+(ln>>2)
    for (int idx = tid; idx < 4096; idx += 256) {
        int kk = idx >> 10;
        int r  = idx & 1023;
        int nt = r >> 6;
        int r2 = r & 63;
        int ln = r2 >> 1, hf = r2 & 1;
        int k  = kk * 8 + (ln & 3) + (hf << 2);
        int n  = nt * 8 + (ln >> 2);
        w1f_sm[idx] = __uint_as_float(tf32_rna(w1[k * 128 + n]));
    }
    // stage w2 [128,64] into tf32 B-frag order
    for (int idx = tid; idx < 8192; idx += 256) {
        int kk = idx >> 9;
        int r  = idx & 511;
        int nt = r >> 6;
        int r2 = r & 63;
        int ln = r2 >> 1, hf = r2 & 1;
        int k  = kk * 8 + (ln & 3) + (hf << 2);
        int n  = nt * 8 + (ln >> 2);
        w2f_sm[idx] = __uint_as_float(tf32_rna(w2[k * 64 + n]));
    }
    if (tid < 128) b1_sm[tid] = b1[tid];
    if (tid < 64) {
        w3_sm[tid] = w3[tid];
        b2_sm[tid] = b2[tid];
    }
    __syncthreads();

    const int lane = tid & 31, wp = tid >> 5;
    const int g2 = lane >> 2, c2 = lane & 3;
    const int m  = wp & 3, nh = wp >> 2;
    const int srow = m * 16 + g2;

    // ---- phase 1 (tensor): h1 = relu(x @ w1 + b1), m16n8k8, K=32 ----
    // warp: 16 rows (m) x 64 cols (nh half of 128): 4 k-steps x 8 n8-tiles
    {
        float acc[8][4];
        #pragma unroll
        for (int nt = 0; nt < 8; ++nt) {
            const int n0 = nh * 64 + nt * 8 + 2 * c2;
            float bA = b1_sm[n0], bB = b1_sm[n0 + 1];
            acc[nt][0] = bA; acc[nt][1] = bB;
            acc[nt][2] = bA; acc[nt][3] = bB;
        }
        #pragma unroll
        for (int kk = 0; kk < 4; ++kk) {
            uint32_t a0 = tf32_rna(in_sm[srow * 36 + kk * 8 + c2]);
            uint32_t a1 = tf32_rna(in_sm[(srow + 8) * 36 + kk * 8 + c2]);
            uint32_t a2 = tf32_rna(in_sm[srow * 36 + kk * 8 + c2 + 4]);
            uint32_t a3 = tf32_rna(in_sm[(srow + 8) * 36 + kk * 8 + c2 + 4]);
            #pragma unroll
            for (int nt = 0; nt < 8; ++nt) {
                uint2 bf = *(const uint2*)&w1f_sm[(size_t)(kk * 16 + nh * 8 + nt) * 64 + lane * 2];
                mma_tf32(acc[nt][0], acc[nt][1], acc[nt][2], acc[nt][3],
                         a0, a1, a2, a3, bf.x, bf.y);
            }
        }
        #pragma unroll
        for (int nt = 0; nt < 8; ++nt) {
            const int n0 = nh * 64 + nt * 8 + 2 * c2;
            float2 rA, rB;
            rA.x = fmaxf(acc[nt][0], 0.0f); rA.y = fmaxf(acc[nt][1], 0.0f);
            rB.x = fmaxf(acc[nt][2], 0.0f); rB.y = fmaxf(acc[nt][3], 0.0f);
            *(float2*)&h1_sm[srow * 132 + n0]       = rA;
            *(float2*)&h1_sm[(srow + 8) * 132 + n0] = rB;
        }
    }
    __syncthreads();

    // ---- phase 2 (tensor): h2 = relu(h1 @ w2 + b2), m16n8k8, K=128 ----
    {
        float acc[4][4];
        #pragma unroll
        for (int nt = 0; nt < 4; ++nt) {
            const int n0 = nh * 32 + nt * 8 + 2 * c2;
            float bA = b2_sm[n0], bB = b2_sm[n0 + 1];
            acc[nt][0] = bA; acc[nt][1] = bB;
            acc[nt][2] = bA; acc[nt][3] = bB;
        }
        #pragma unroll 4
        for (int kk = 0; kk < 16; ++kk) {
            uint32_t a0 = tf32_rna(h1_sm[srow * 132 + kk * 8 + c2]);
            uint32_t a1 = tf32_rna(h1_sm[(srow + 8) * 132 + kk * 8 + c2]);
            uint32_t a2 = tf32_rna(h1_sm[srow * 132 + kk * 8 + c2 + 4]);
            uint32_t a3 = tf32_rna(h1_sm[(srow + 8) * 132 + kk * 8 + c2 + 4]);
            #pragma unroll
            for (int nt = 0; nt < 4; ++nt) {
                uint2 bf = *(const uint2*)&w2f_sm[(size_t)(kk * 8 + nh * 4 + nt) * 64 + lane * 2];
                mma_tf32(acc[nt][0], acc[nt][1], acc[nt][2], acc[nt][3],
                         a0, a1, a2, a3, bf.x, bf.y);
            }
        }
        #pragma unroll
        for (int nt = 0; nt < 4; ++nt) {
            const int n0 = nh * 32 + nt * 8 + 2 * c2;
            h2_sm[srow * 68 + n0]           = fmaxf(acc[nt][0], 0.0f);
            h2_sm[srow * 68 + n0 + 1]       = fmaxf(acc[nt][1], 0.0f);
            h2_sm[(srow + 8) * 68 + n0]     = fmaxf(acc[nt][2], 0.0f);
            h2_sm[(srow + 8) * 68 + n0 + 1] = fmaxf(acc[nt][3], 0.0f);
        }
    }
    __syncthreads();

    // ---- phase 3 (SIMT): out = h2 · w3 + b3, 4 threads/sample ----
    {
        const int s = tid >> 2, q = tid & 3;
        const float4* hr = (const float4*)(h2_sm + s * 68 + q * 16);
        const float4* wr = (const float4*)(w3_sm + q * 16);
        float acc = 0.0f;
        #pragma unroll
        for (int i = 0; i < 4; ++i) {
            float4 h = hr[i], w = wr[i];
            acc = fmaf(h.x, w.x, acc);
            acc = fmaf(h.y, w.y, acc);
            acc = fmaf(h.z, w.z, acc);
            acc = fmaf(h.w, w.w, acc);
        }
        acc += __shfl_xor_sync(0xffffffffu, acc, 1);
        acc += __shfl_xor_sync(0xffffffffu, acc, 2);
        if (q == 0)
            g_partial[(PK_NCHUNK + part) * BATCH + g0 + s] = acc + b3[0];
    }

    // ---- arrival + (maybe) fused final reduction ----
    {
        __shared__ int last;
        const int pt = tile >> 2;            // 256-sample tile index
        __threadfence();
        __syncthreads();
        if (tid == 0)
            last = (atomicAdd(&g_cnt[pt], 1) == ARRIVALS - 1) ? 1 : 0;
        __syncthreads();
        if (last) {
            __threadfence();
            const int base = pt * 256;
            out[base + tid] = reduce_sample(base + tid);
            __syncthreads();
            if (tid == 0) g_cnt[pt] = 0;     // reset for next graph replay
        }
    }
}

// ---------------------------------------------------------------------------
// Kernel 2: structured interaction + per-pair MLPs via tf32 mma, pairs-outer.
// grid = (32 sample tiles of 256, 32 chunks) = 1024 CTAs, 128 threads.
// R9 loop body (proven best) + fused-reduction arrival epilogue. (R14 verbatim)
// ---------------------------------------------------------------------------
__global__ __launch_bounds__(128, 6)
void pair_kernel(float* __restrict__ out,
                 const float* __restrict__ xzw, const float* __restrict__ xzb,
                 const float* __restrict__ pw1, const float* __restrict__ pb1,
                 const float* __restrict__ pw2)
{
    __shared__ __align__(16) ull   x2_sm[256];         // dup-packed x column (2KB)
    __shared__ __align__(16) float wq_sm[1024];        // [pair][c]{wx_c,wx_c4,wz_c,wz_c4,bb_c,bb_c4,0,0}
    __shared__ __align__(16) float bf_sm[4096];        // pw1 tf32 B-frags
    __shared__ __align__(16) float ep_sm[1024];        // [pair][cp]{pb,pb,pw2,pw2}

    const int tid   = threadIdx.x;
    const int tile  = blockIdx.x;    // 0..31
    const int chunk = blockIdx.y;    // 0..31
    const int g0    = tile * 256;
    const int p0    = chunk * 32;

    // ---- staging ----
    for (int idx = tid; idx < 256; idx += 128) {
        float xv = g_xT[(size_t)chunk * BATCH + g0 + idx];
        x2_sm[idx] = pack2(xv, xv);
    }
    for (int idx = tid; idx < 1024; idx += 128) {
        int pr = idx >> 5, c = (idx >> 3) & 3, e = idx & 7;
        int p  = p0 + pr;
        int j  = c + ((e & 1) << 2);
        float v = 0.f;
        if (e < 2)      v = xzw[(size_t)chunk * OUT_U + p * 8 + j];
        else if (e < 4) v = xzw[(size_t)(32 + pr) * OUT_U + p * 8 + j];
        else if (e < 6) v = xzb[p * 8 + j];
        wq_sm[idx] = v;
    }
    for (int idx = tid; idx < 4096; idx += 128) {
        int pr = idx >> 7, r = idx & 127;
        int nm = r >> 6, r2 = r & 63;
        int ln = r2 >> 1, half = r2 & 1;
        int k = (ln & 3) + (half << 2);
        int n = (ln >> 2) + (nm << 3);
        bf_sm[idx] = __uint_as_float(tf32_rna(pw1[(size_t)(p0 + pr) * 128 + k * 16 + n]));
    }
    for (int idx = tid; idx < 1024; idx += 128) {
        int pr = idx >> 5, r = idx & 31;
        int cp = r >> 2, e = r & 3;
        int col = 2 * cp + (e & 1);
        ep_sm[idx] = (e < 2) ? pb1[(p0 + pr) * 16 + col]
                             : pw2[(p0 + pr) * 16 + col];
    }
    __syncthreads();

    const int lane = tid & 31, w = tid >> 5;   // w 0..3
    const int g = lane >> 2, c = lane & 3;
    const int sbase = w * 64;                  // warp's sample base within tile

    float outv[8];
    #pragma unroll
    for (int i = 0; i < 8; ++i) outv[i] = 0.f;

    const float* zT = g_zT + g0;

    #pragma unroll 1
    for (int pl = 0; pl < 32; ++pl) {
        // per-pair registers (reused across 4 subtiles)
        ulonglong2 wu = *(const ulonglong2*)&wq_sm[(pl * 4 + c) * 8];
        ull bbu = *(const ull*)&wq_sm[(pl * 4 + c) * 8 + 4];
        uint2 bf0 = *(const uint2*)&bf_sm[pl * 128 + lane * 2];
        uint2 bf1 = *(const uint2*)&bf_sm[pl * 128 + 64 + lane * 2];
        float4 e0 = *(const float4*)&ep_sm[(pl * 8 + c) * 4];
        float4 e1 = *(const float4*)&ep_sm[(pl * 8 + c + 4) * 4];
        const float* zcol = zT + (size_t)pl * BATCH;

        #pragma unroll
        for (int sub = 0; sub < 4; ++sub) {
            const int srow = sbase + sub * 16 + g;
            float zg  = zcol[srow];
            float zg8 = zcol[srow + 8];

            // h in A-frag layout: rows {g, g+8} x cols {c, c+4}
            ull hg  = fma2(wu.x, x2_sm[srow],     fma2(wu.y, pack2(zg,  zg),  bbu));
            ull hg8 = fma2(wu.x, x2_sm[srow + 8], fma2(wu.y, pack2(zg8, zg8), bbu));
            float h0, h2, h1, h3;
            unpack2(hg,  h0, h2);
            unpack2(hg8, h1, h3);
            // raw fp32 bits: tf32 shares fp32 layout; MMA ignores low mantissa
            uint32_t a0 = __float_as_uint(fmaxf(h0, 0.f));
            uint32_t a1 = __float_as_uint(fmaxf(h1, 0.f));
            uint32_t a2 = __float_as_uint(fmaxf(h2, 0.f));
            uint32_t a3 = __float_as_uint(fmaxf(h3, 0.f));

            // t = h @ pw1 + pb1
            float d0 = e0.x, d1 = e0.y, d2 = e0.x, d3 = e0.y;
            mma_tf32(d0, d1, d2, d3, a0, a1, a2, a3, bf0.x, bf0.y);
            float f0 = e1.x, f1 = e1.y, f2 = e1.x, f3 = e1.y;
            mma_tf32(f0, f1, f2, f3, a0, a1, a2, a3, bf1.x, bf1.y);

            // out += relu(t) . pw2
            outv[2*sub]   = fmaf(fmaxf(d0, 0.f), e0.z, outv[2*sub]);
            outv[2*sub]   = fmaf(fmaxf(d1, 0.f), e0.w, outv[2*sub]);
            outv[2*sub]   = fmaf(fmaxf(f0, 0.f), e1.z, outv[2*sub]);
            outv[2*sub]   = fmaf(fmaxf(f1, 0.f), e1.w, outv[2*sub]);
            outv[2*sub+1] = fmaf(fmaxf(d2, 0.f), e0.z, outv[2*sub+1]);
            outv[2*sub+1] = fmaf(fmaxf(d3, 0.f), e0.w, outv[2*sub+1]);
            outv[2*sub+1] = fmaf(fmaxf(f2, 0.f), e1.z, outv[2*sub+1]);
            outv[2*sub+1] = fmaf(fmaxf(f3, 0.f), e1.w, outv[2*sub+1]);
        }
    }

    // reduce over the 4 col-partition threads of each row group
    #pragma unroll
    for (int i = 0; i < 8; ++i) {
        outv[i] += __shfl_xor_sync(0xffffffffu, outv[i], 1);
        outv[i] += __shfl_xor_sync(0xffffffffu, outv[i], 2);
    }
    if (c == 0) {
        #pragma unroll
        for (int sub = 0; sub < 4; ++sub) {
            g_partial[(size_t)chunk * BATCH + g0 + sbase + sub * 16 + g]     = outv[2*sub];
            g_partial[(size_t)chunk * BATCH + g0 + sbase + sub * 16 + g + 8] = outv[2*sub + 1];
        }
    }

    // ---- arrival + (maybe) fused final reduction ----
    {
        __shared__ int last;
        __threadfence();
        __syncthreads();
        if (tid == 0)
            last = (atomicAdd(&g_cnt[tile], 1) == ARRIVALS - 1) ? 1 : 0;
        __syncthreads();
        if (last) {
            __threadfence();
            for (int s = tid; s < 256; s += 128)
                out[g0 + s] = reduce_sample(g0 + s);
            __syncthreads();
            if (tid == 0) g_cnt[tile] = 0;   // reset for next graph replay
        }
    }
}

// ---------------------------------------------------------------------------
extern "C" void kernel_launch(void* const* d_in, const int* in_sizes, int n_in,
                              void* d_out, int out_size)
{
    const float* x   = (const float*)d_in[0];
    const float* z   = (const float*)d_in[1];
    const float* xw1 = (const float*)d_in[2];
    const float* xb1 = (const float*)d_in[3];
    const float* xw2 = (const float*)d_in[4];
    const float* xb2 = (const float*)d_in[5];
    const float* xw3 = (const float*)d_in[6];
    const float* xb3 = (const float*)d_in[7];
    const float* zw1 = (const float*)d_in[8];
    const float* zb1 = (const float*)d_in[9];
    const float* zw2 = (const float*)d_in[10];
    const float* zb2 = (const float*)d_in[11];
    const float* zw3 = (const float*)d_in[12];
    const float* zb3 = (const float*)d_in[13];
    const float* xzw = (const float*)d_in[14];
    const float* xzb = (const float*)d_in[15];
    const float* pw1 = (const float*)d_in[16];
    const float* pb1 = (const float*)d_in[17];
    const float* pw2 = (const float*)d_in[18];
    float* out = (float*)d_out;

    static cudaStream_t s2 = nullptr;
    static cudaEvent_t  e_fork = nullptr, e_join = nullptr;
    if (s2 == nullptr) {
        cudaStreamCreateWithFlags(&s2, cudaStreamNonBlocking);
        cudaEventCreateWithFlags(&e_fork, cudaEventDisableTiming);
        cudaEventCreateWithFlags(&e_join, cudaEventDisableTiming);
        cudaFuncSetAttribute(pair_kernel,
            cudaFuncAttributePreferredSharedMemoryCarveout, 100);
    }

    const size_t smem_mlp = 27648u * sizeof(float);   // 110592 B
    cudaFuncSetAttribute(mlp_kernel, cudaFuncAttributeMaxDynamicSharedMemorySize, (int)smem_mlp);

    // fork: mlp on side stream (its CTAs also feed the fused reduction)
    cudaEventRecord(e_fork, 0);
    cudaStreamWaitEvent(s2, e_fork, 0);
    mlp_kernel<<<dim3(MK_NTILE, 2), 256, smem_mlp, s2>>>(out, x, z,
        xw1, xb1, xw2, xb2, xw3, xb3,
        zw1, zb1, zw2, zb2, zw3, zb3);
    cudaEventRecord(e_join, s2);

    transpose_kernel<<<BATCH / 64, 256>>>(x, z);
    pair_kernel<<<dim3(32, 32), 128>>>(out, xzw, xzb, pw1, pb1, pw2);

    // join side stream so the captured graph's completion covers mlp's writes
    cudaStreamWaitEvent(0, e_join, 0);
}